// round 4
// baseline (speedup 1.0000x reference)
#include <cuda_runtime.h>
#include <cstdint>

// ---------------- problem constants ----------------
#define K_CODES   1024
#define D_DIM     128
#define N_TOK     65536        // 64 * 32 * 32 tokens (BHWC order)
#define Z_ELEMS   8388608      // 64 * 128 * 32 * 32
#define EMA       0.99f
#define EPSV      1e-5f
#define EPS_FLAG  1e-3f        // gap threshold for exact recompute

// ---------------- output layout (flattened reference tuple, fp32) ----------------
#define Q_OFF     0
#define IDX_OFF   8388608
#define L_OFF     8454144
#define CB_OFF    8454146
#define CNT_OFF   8585218
#define EMW_OFF   8586242

// ---------------- smem layout (bytes) ----------------
#define SM_A      0            // 16384 floats (64KB)  z fp32, fragment order
#define SM_B      65536        // 2 stages * 16384 floats (128KB) cb hi/lo frag order
#define SM_CN     196608       // 1024 floats
#define SM_REDV   200704       // 256 floats (best)
#define SM_REDI   201728       // 256 ints  (best idx)
#define SM_RED2   202752       // 256 floats (second best)
#define SM_TOTAL  203776

// ---------------- global scratch ----------------
__device__ float g_zA[N_TOK * D_DIM];          // fragment-ordered z (33.5MB)
__device__ float g_cbB[2 * K_CODES * D_DIM];   // hi/lo fragment-ordered codebook (1MB)
__device__ float g_cnorm[K_CODES];
__device__ float g_counts[K_CODES];
__device__ float g_dw[K_CODES * D_DIM];
__device__ int   g_idx[N_TOK];
__device__ float g_loss;
__device__ float g_weights[K_CODES];
__device__ int   g_fixcnt;
__device__ int   g_fixlist[N_TOK];

// ---------------- helpers ----------------
__device__ __forceinline__ uint32_t smem_u32(const void* p) {
    uint32_t a;
    asm("{ .reg .u64 t; cvta.to.shared.u64 t, %1; cvt.u32.u64 %0, t; }" : "=r"(a) : "l"(p));
    return a;
}
__device__ __forceinline__ uint32_t tf32_rna(float v) {
    uint32_t r;
    asm("cvt.rna.tf32.f32 %0, %1;" : "=r"(r) : "f"(v));
    return r;
}
__device__ __forceinline__ void mma8(float* c, const uint32_t* a, const uint32_t* b) {
    asm volatile("mma.sync.aligned.m16n8k8.row.col.f32.tf32.tf32.f32 "
                 "{%0,%1,%2,%3}, {%4,%5,%6,%7}, {%8,%9}, {%0,%1,%2,%3};"
                 : "+f"(c[0]), "+f"(c[1]), "+f"(c[2]), "+f"(c[3])
                 : "r"(a[0]), "r"(a[1]), "r"(a[2]), "r"(a[3]), "r"(b[0]), "r"(b[1]));
}
// merge candidate (v,id) into triple (b1,i1,b2); first-index tie-break
__device__ __forceinline__ void merge3(float& b1, int& i1, float& b2, float v, int id) {
    if (v < b1 || (v == b1 && id < i1)) { b2 = b1; b1 = v; i1 = id; }
    else if (v < b2) b2 = v;
}
#define CP16(dst, src) \
    asm volatile("cp.async.cg.shared.global [%0], [%1], 16;" :: "r"(dst), "l"(src) : "memory")
#define CP_COMMIT() asm volatile("cp.async.commit_group;" ::: "memory")
#define CP_WAIT1()  asm volatile("cp.async.wait_group 1;" ::: "memory")
#define CP_WAIT0()  asm volatile("cp.async.wait_group 0;" ::: "memory")

// ---------------- zero scratch ----------------
__global__ void zero_kernel() {
    int i = blockIdx.x * blockDim.x + threadIdx.x;
    if (i < K_CODES * D_DIM) g_dw[i] = 0.f;
    if (i < K_CODES)         g_counts[i] = 0.f;
    if (i == 0)            { g_loss = 0.f; g_fixcnt = 0; }
}

// ---------------- codebook squared norms ----------------
__global__ void prep_norm_kernel(const float* __restrict__ cb) {
    int k = blockIdx.x, d = threadIdx.x;
    float v = cb[k * D_DIM + d];
    float sq = v * v;
    #pragma unroll
    for (int o = 16; o; o >>= 1) sq += __shfl_xor_sync(0xffffffffu, sq, o);
    __shared__ float ws[4];
    if ((d & 31) == 0) ws[d >> 5] = sq;
    __syncthreads();
    if (d == 0) g_cnorm[k] = ws[0] + ws[1] + ws[2] + ws[3];
}

// ---------------- z -> fragment-ordered fp32 scratch ----------------
// Per 128-token CTA block: [f(8 m16-frags)][s(16 k-steps)][lane(32)][e(4)]
__global__ void prep_z_kernel(const float* __restrict__ z) {
    int i = blockIdx.x * blockDim.x + threadIdx.x;   // linear over z (b,d,spix)
    int spix = i & 1023;
    int d    = (i >> 10) & 127;
    int b    = i >> 17;
    int n    = (b << 10) + spix;                     // BHWC token id
    int ctaM = n >> 7, t = n & 127;
    int f = t >> 4, rr = t & 15;
    int s = d >> 3, cc = d & 7;
    int lane = (rr & 7) * 4 + (cc & 3);
    int e    = (rr >> 3) + 2 * (cc >> 2);
    g_zA[ctaM * 16384 + (f * 16 + s) * 128 + lane * 4 + e] = z[i];
}

// ---------------- codebook -> tf32 hi/lo fragment-ordered scratch ----------------
__global__ void prep_cb_kernel(const float* __restrict__ cb) {
    int i = blockIdx.x * blockDim.x + threadIdx.x;   // < 131072
    int d = i & 127;
    int k = i >> 7;
    float v  = cb[i];
    uint32_t hb = tf32_rna(v);
    float hi = __uint_as_float(hb);
    float lo = v - hi;                                // exact
    int tile = k >> 6, c = k & 63;
    int nf = c >> 3, np = nf >> 1, half = nf & 1;
    int nif = c & 7;
    int s = d >> 3, kk = d & 7;
    int lane = nif * 4 + (kk & 3);
    int q    = half * 2 + (kk >> 2);
    int base = (((tile * 2) * 16 + s) * 4 + np) * 128 + lane * 4 + q;
    g_cbB[base]        = hi;
    g_cbB[base + 8192] = lo;
}

// ---------------- mma distance GEMM + argmin (tracks best + 2nd best) ----------------
__global__ void __launch_bounds__(256, 1) argmin_mma_kernel() {
    extern __shared__ char smem[];
    const uint32_t smb = smem_u32(smem);
    const int tid = threadIdx.x;
    const int l   = tid & 31, w = tid >> 5;
    const int wr  = w & 3,    wc = w >> 2;
    const int lq  = l & 3,    lr = l >> 2;
    const int ctaM = blockIdx.x;

    {
        const float* gA = g_zA + (size_t)ctaM * 16384;
        #pragma unroll
        for (int j = 0; j < 16; j++) {
            int c = j * 256 + tid;
            CP16(smb + SM_A + c * 16, gA + c * 4);
        }
        CP16(smb + SM_CN + tid * 16, g_cnorm + tid * 4);
        CP_COMMIT();
    }
    {
        const float* gB = g_cbB;
        #pragma unroll
        for (int j = 0; j < 16; j++) {
            int c = j * 256 + tid;
            CP16(smb + SM_B + c * 16, gB + c * 4);
        }
        CP_COMMIT();
    }

    float acc[2][4][4];
    #pragma unroll
    for (int m = 0; m < 2; m++)
        #pragma unroll
        for (int n = 0; n < 4; n++)
            #pragma unroll
            for (int e = 0; e < 4; e++) acc[m][n][e] = 0.f;

    float best [2][2] = {{3.4e38f, 3.4e38f}, {3.4e38f, 3.4e38f}};
    float best2[2][2] = {{3.4e38f, 3.4e38f}, {3.4e38f, 3.4e38f}};
    int   bidx [2][2] = {{0, 0}, {0, 0}};

    for (int t = 0; t < 16; t++) {
        if (t < 15) {
            const float* gB = g_cbB + (t + 1) * 16384;
            uint32_t dst = smb + SM_B + ((t + 1) & 1) * 65536;
            #pragma unroll
            for (int j = 0; j < 16; j++) {
                int c = j * 256 + tid;
                CP16(dst + c * 16, gB + c * 4);
            }
            CP_COMMIT();
            CP_WAIT1();
        } else {
            CP_WAIT0();
        }
        __syncthreads();

        const float4* As4 = (const float4*)(smem + SM_A);
        const float4* Bs4 = (const float4*)(smem + SM_B + (size_t)(t & 1) * 65536);

        #pragma unroll
        for (int s = 0; s < 16; s++) {
            float4 a0 = As4[((wr * 2 + 0) * 16 + s) * 32 + l];
            float4 a1 = As4[((wr * 2 + 1) * 16 + s) * 32 + l];
            uint32_t ah[2][4], al[2][4];
            {
                float av[2][4] = {{a0.x, a0.y, a0.z, a0.w}, {a1.x, a1.y, a1.z, a1.w}};
                #pragma unroll
                for (int m = 0; m < 2; m++)
                    #pragma unroll
                    for (int e = 0; e < 4; e++) {
                        uint32_t h = tf32_rna(av[m][e]);
                        ah[m][e] = h;
                        al[m][e] = __float_as_uint(av[m][e] - __uint_as_float(h));
                    }
            }
            float4 bh0 = Bs4[((0 * 16 + s) * 4 + wc * 2 + 0) * 32 + l];
            float4 bh1 = Bs4[((0 * 16 + s) * 4 + wc * 2 + 1) * 32 + l];
            float4 bl0 = Bs4[((1 * 16 + s) * 4 + wc * 2 + 0) * 32 + l];
            float4 bl1 = Bs4[((1 * 16 + s) * 4 + wc * 2 + 1) * 32 + l];
            uint32_t bh[4][2] = {
                {__float_as_uint(bh0.x), __float_as_uint(bh0.y)},
                {__float_as_uint(bh0.z), __float_as_uint(bh0.w)},
                {__float_as_uint(bh1.x), __float_as_uint(bh1.y)},
                {__float_as_uint(bh1.z), __float_as_uint(bh1.w)}};
            uint32_t bl[4][2] = {
                {__float_as_uint(bl0.x), __float_as_uint(bl0.y)},
                {__float_as_uint(bl0.z), __float_as_uint(bl0.w)},
                {__float_as_uint(bl1.x), __float_as_uint(bl1.y)},
                {__float_as_uint(bl1.z), __float_as_uint(bl1.w)}};

            #pragma unroll
            for (int m = 0; m < 2; m++)
                #pragma unroll
                for (int n = 0; n < 4; n++) {
                    mma8(acc[m][n], ah[m], bh[n]);   // hi*hi
                    mma8(acc[m][n], ah[m], bl[n]);   // hi*lo
                    mma8(acc[m][n], al[m], bh[n]);   // lo*hi
                }
        }

        const float* cn = (const float*)(smem + SM_CN);
        #pragma unroll
        for (int m = 0; m < 2; m++)
            #pragma unroll
            for (int n = 0; n < 4; n++)
                #pragma unroll
                for (int e = 0; e < 4; e++) {
                    int code = t * 64 + (wc * 4 + n) * 8 + lq * 2 + (e & 1);
                    float dist = fmaf(-2.f, acc[m][n][e], cn[code]);
                    int rb = e >> 1;
                    merge3(best[m][rb], bidx[m][rb], best2[m][rb], dist, code);
                    acc[m][n][e] = 0.f;
                }
        __syncthreads();
    }

    // quad reduction (lanes xor 1,2 share rows, differ in cols)
    float* redv = (float*)(smem + SM_REDV);
    int*   redi = (int*)(smem + SM_REDI);
    float* red2 = (float*)(smem + SM_RED2);
    #pragma unroll
    for (int m = 0; m < 2; m++)
        #pragma unroll
        for (int rb = 0; rb < 2; rb++) {
            float v1 = best[m][rb], v2 = best2[m][rb];
            int   id = bidx[m][rb];
            #pragma unroll
            for (int off = 1; off <= 2; off <<= 1) {
                float ov1 = __shfl_xor_sync(0xffffffffu, v1, off);
                float ov2 = __shfl_xor_sync(0xffffffffu, v2, off);
                int   oi  = __shfl_xor_sync(0xffffffffu, id, off);
                merge3(v1, id, v2, ov1, oi);
                merge3(v1, id, v2, ov2, 0x7fffffff);
            }
            if (lq == 0) {
                int row = wr * 32 + m * 16 + rb * 8 + lr;
                redv[wc * 128 + row] = v1;
                redi[wc * 128 + row] = id;
                red2[wc * 128 + row] = v2;
            }
        }
    __syncthreads();
    if (tid < 128) {
        float v1 = redv[tid],       s1 = red2[tid];
        float w1 = redv[128 + tid], w2 = red2[128 + tid];
        int   i1 = redi[tid],       j1 = redi[128 + tid];
        merge3(v1, i1, s1, w1, j1);
        merge3(v1, i1, s1, w2, 0x7fffffff);
        int token = ctaM * 128 + tid;
        g_idx[token] = i1;
        if (s1 - v1 < EPS_FLAG) {
            int p = atomicAdd(&g_fixcnt, 1);
            g_fixlist[p] = token;
        }
    }
}

// ---------------- exact fp32 recompute for near-tie tokens ----------------
// Fixed grid (graph-safe); count read on device. One 128-thread block per token.
__global__ void fixup_kernel(const float* __restrict__ z,
                             const float* __restrict__ cb) {
    __shared__ float zz[D_DIM];
    __shared__ float rv[4];
    __shared__ int   ri[4];
    int cnt = g_fixcnt;
    for (int it = blockIdx.x; it < cnt; it += gridDim.x) {
        int token = g_fixlist[it];
        int b = token >> 10, s = token & 1023;
        int d = threadIdx.x;
        zz[d] = z[(size_t)b * 131072 + (size_t)d * 1024 + s];
        __syncthreads();

        float bv = 3.4e38f;
        int   bi = 0;
        #pragma unroll 1
        for (int j = 0; j < 8; j++) {
            int k = d * 8 + j;                 // thread covers ascending codes
            const float* cp = &cb[k * D_DIM];
            float dot = 0.f;
            #pragma unroll
            for (int q = 0; q < D_DIM; q++) dot = fmaf(zz[q], cp[q], dot);
            float dist = fmaf(-2.f, dot, g_cnorm[k]);
            if (dist < bv) { bv = dist; bi = k; }
        }
        // block reduce with first-index tie-break
        #pragma unroll
        for (int off = 16; off; off >>= 1) {
            float ov = __shfl_xor_sync(0xffffffffu, bv, off);
            int   oi = __shfl_xor_sync(0xffffffffu, bi, off);
            if (ov < bv || (ov == bv && oi < bi)) { bv = ov; bi = oi; }
        }
        if ((d & 31) == 0) { rv[d >> 5] = bv; ri[d >> 5] = bi; }
        __syncthreads();
        if (d == 0) {
            for (int q = 1; q < 4; q++)
                if (rv[q] < bv || (rv[q] == bv && ri[q] < bi)) { bv = rv[q]; bi = ri[q]; }
            g_idx[token] = bi;
        }
        __syncthreads();
    }
}

// ---------------- gather quantized + loss + counts + idx output ----------------
__global__ void quant_kernel(const float* __restrict__ z,
                             const float* __restrict__ cb,
                             float* __restrict__ out) {
    int n    = blockIdx.x * 8 + (threadIdx.x >> 5);
    int lane = threadIdx.x & 31;
    int k    = g_idx[n];

    float4 q = *(const float4*)&cb[k * D_DIM + lane * 4];
    size_t off = (size_t)n * D_DIM + lane * 4;
    *(float4*)&out[Q_OFF + off] = q;

    float4 zz = *(const float4*)&z[off];
    float dx = q.x - zz.x, dy = q.y - zz.y, dz = q.z - zz.z, dw = q.w - zz.w;
    float s = dx * dx + dy * dy + dz * dz + dw * dw;
    #pragma unroll
    for (int o = 16; o; o >>= 1) s += __shfl_xor_sync(0xffffffffu, s, o);

    __shared__ float ws[8];
    if (lane == 0) {
        ws[threadIdx.x >> 5] = s;
        atomicAdd(&g_counts[k], 1.f);
        out[IDX_OFF + n] = (float)k;
    }
    __syncthreads();
    if (threadIdx.x == 0) {
        float t = 0.f;
        #pragma unroll
        for (int i = 0; i < 8; i++) t += ws[i];
        atomicAdd(&g_loss, t);
    }
}

// ---------------- dw scatter ----------------
__global__ void dw_kernel(const float* __restrict__ z) {
    int i = blockIdx.x * blockDim.x + threadIdx.x;
    int s = i & 1023;
    int d = (i >> 10) & 127;
    int b = i >> 17;
    int n = (b << 10) + s;
    int k = g_idx[n];
    atomicAdd(&g_dw[k * D_DIM + d], z[i]);
}

// ---------------- EMA count update + weights + losses ----------------
__global__ void finalize1_kernel(const float* __restrict__ ema_count,
                                 float* __restrict__ out) {
    int k = threadIdx.x;
    float c = EMA * ema_count[k] + (1.f - EMA) * g_counts[k];
    out[CNT_OFF + k] = c;

    __shared__ float sm[1024];
    sm[k] = c;
    __syncthreads();
    for (int o = 512; o; o >>= 1) {
        if (k < o) sm[k] += sm[k + o];
        __syncthreads();
    }
    float n = sm[0];
    g_weights[k] = (c + EPSV) / (n + K_CODES * EPSV) * n;

    if (k == 0) {
        float L = g_loss / 8388608.f;
        out[L_OFF]     = L;
        out[L_OFF + 1] = L;
    }
}

// ---------------- EMA weight update + new codebook ----------------
__global__ void finalize2_kernel(const float* __restrict__ ema_weight,
                                 float* __restrict__ out) {
    int i = blockIdx.x * blockDim.x + threadIdx.x;
    int k = i >> 7;
    float w = EMA * ema_weight[i] + (1.f - EMA) * g_dw[i];
    out[EMW_OFF + i] = w;
    out[CB_OFF + i]  = w / g_weights[k];
}

// ---------------- launch ----------------
extern "C" void kernel_launch(void* const* d_in, const int* in_sizes, int n_in,
                              void* d_out, int out_size) {
    const float* z          = (const float*)d_in[0];
    const float* cb         = (const float*)d_in[1];
    const float* ema_count  = (const float*)d_in[2];
    const float* ema_weight = (const float*)d_in[3];
    float* out = (float*)d_out;

    cudaFuncSetAttribute(argmin_mma_kernel,
                         cudaFuncAttributeMaxDynamicSharedMemorySize, SM_TOTAL);

    zero_kernel<<<512, 256>>>();
    prep_norm_kernel<<<K_CODES, D_DIM>>>(cb);
    prep_z_kernel<<<Z_ELEMS / 256, 256>>>(z);
    prep_cb_kernel<<<512, 256>>>(cb);
    argmin_mma_kernel<<<N_TOK / 128, 256, SM_TOTAL>>>();
    fixup_kernel<<<128, 128>>>(z, cb);
    quant_kernel<<<N_TOK / 8, 256>>>(z, cb, out);
    dw_kernel<<<Z_ELEMS / 256, 256>>>(z);
    finalize1_kernel<<<1, 1024>>>(ema_count, out);
    finalize2_kernel<<<512, 256>>>(ema_weight, out);
}

// round 5
// speedup vs baseline: 1.3211x; 1.3211x over previous
#include <cuda_runtime.h>
#include <cuda_bf16.h>
#include <cstdint>

// ---------------- problem constants ----------------
#define K_CODES   1024
#define D_DIM     128
#define N_TOK     65536        // 64 * 32 * 32 tokens (BHWC order)
#define Z_ELEMS   8388608      // 64 * 128 * 32 * 32
#define EMA       0.99f
#define EPSV      1e-5f
#define EPS_FLAG  2e-3f        // gap threshold for exact recompute

// ---------------- output layout (flattened reference tuple, fp32) ----------------
#define Q_OFF     0
#define IDX_OFF   8388608
#define L_OFF     8454144
#define CB_OFF    8454146
#define CNT_OFF   8585218
#define EMW_OFF   8586242

// ---------------- smem layout for argmin (bytes) ----------------
#define SM_A      0            // 64KB: A hi (32KB) + A lo (32KB), frag-packed
#define SM_B      65536        // 2 stages * 32KB (hi 16KB + lo 16KB each)
#define SM_CN     131072       // 1024 floats
#define SM_REDV   135168       // 256 floats (best)
#define SM_REDI   136192       // 256 ints  (best idx)
#define SM_RED2   137216       // 256 floats (second best)
#define SM_TOTAL  138240

// ---------------- global scratch ----------------
__device__ uint4    g_Ah[512 * 2048];     // z hi, frag-packed [cta][f8][s8][lane32] (16.7MB)
__device__ uint4    g_Al[512 * 2048];     // z lo
__device__ uint32_t g_Bh[65536];          // cb hi [tile16][s8][np4][lane32][comp4] (256KB)
__device__ uint32_t g_Bl[65536];          // cb lo
__device__ float    g_cnorm[K_CODES];
__device__ float    g_counts[K_CODES];
__device__ float    g_dw[K_CODES * D_DIM];
__device__ int      g_idx[N_TOK];
__device__ float    g_loss;
__device__ float    g_weights[K_CODES];
__device__ int      g_fixcnt;
__device__ int      g_fixlist[N_TOK];

// ---------------- helpers ----------------
__device__ __forceinline__ uint32_t smem_u32(const void* p) {
    uint32_t a;
    asm("{ .reg .u64 t; cvta.to.shared.u64 t, %1; cvt.u32.u64 %0, t; }" : "=r"(a) : "l"(p));
    return a;
}
__device__ __forceinline__ uint32_t packbf(float a, float b) {
    __nv_bfloat162 t = __floats2bfloat162_rn(a, b);   // x=a (low), y=b (high)
    return *(uint32_t*)&t;
}
__device__ __forceinline__ void mma16(float* c, const uint32_t* a, const uint32_t* b) {
    asm volatile("mma.sync.aligned.m16n8k16.row.col.f32.bf16.bf16.f32 "
                 "{%0,%1,%2,%3}, {%4,%5,%6,%7}, {%8,%9}, {%0,%1,%2,%3};"
                 : "+f"(c[0]), "+f"(c[1]), "+f"(c[2]), "+f"(c[3])
                 : "r"(a[0]), "r"(a[1]), "r"(a[2]), "r"(a[3]), "r"(b[0]), "r"(b[1]));
}
// merge candidate (v,id) into triple (b1,i1,b2); first-index tie-break
__device__ __forceinline__ void merge3(float& b1, int& i1, float& b2, float v, int id) {
    if (v < b1 || (v == b1 && id < i1)) { b2 = b1; b1 = v; i1 = id; }
    else if (v < b2) b2 = v;
}
#define CP16(dst, src) \
    asm volatile("cp.async.cg.shared.global [%0], [%1], 16;" :: "r"(dst), "l"(src) : "memory")
#define CP_COMMIT() asm volatile("cp.async.commit_group;" ::: "memory")
#define CP_WAIT1()  asm volatile("cp.async.wait_group 1;" ::: "memory")
#define CP_WAIT0()  asm volatile("cp.async.wait_group 0;" ::: "memory")

// ---------------- zero scratch ----------------
__global__ void zero_kernel() {
    int i = blockIdx.x * blockDim.x + threadIdx.x;
    if (i < K_CODES * D_DIM) g_dw[i] = 0.f;
    if (i < K_CODES)         g_counts[i] = 0.f;
    if (i == 0)            { g_loss = 0.f; g_fixcnt = 0; }
}

// ---------------- codebook squared norms (exact fp32) ----------------
__global__ void prep_norm_kernel(const float* __restrict__ cb) {
    int k = blockIdx.x, d = threadIdx.x;
    float v = cb[k * D_DIM + d];
    float sq = v * v;
    #pragma unroll
    for (int o = 16; o; o >>= 1) sq += __shfl_xor_sync(0xffffffffu, sq, o);
    __shared__ float ws[4];
    if ((d & 31) == 0) ws[d >> 5] = sq;
    __syncthreads();
    if (d == 0) g_cnorm[k] = ws[0] + ws[1] + ws[2] + ws[3];
}

// ---------------- z -> bf16 hi/lo, mma-fragment-packed ----------------
// One CTA per 128-token block. Load z tile (coalesced) into padded smem,
// then emit uint4 fragments (coalesced writes, conflict-free smem reads).
#define ZT_STRIDE 132
__global__ void __launch_bounds__(256) prep_z_kernel(const float* __restrict__ z) {
    extern __shared__ float zt[];                     // [128 d][ZT_STRIDE]
    const int tid  = threadIdx.x;
    const int ctaM = blockIdx.x;
    const int b  = ctaM >> 3;
    const int s0 = (ctaM & 7) << 7;
    const float* zp = z + (size_t)b * 131072 + s0;

    // load 128x128 tile: zt[d][t] = z[b, d, s0+t]
    #pragma unroll
    for (int j = 0; j < 16; j++) {
        int u  = j * 256 + tid;                       // < 4096 float4 units
        int d  = u >> 5, t4 = (u & 31) << 2;
        float4 v = *(const float4*)&zp[(size_t)d * 1024 + t4];
        *(float4*)&zt[d * ZT_STRIDE + t4] = v;
    }
    __syncthreads();

    // emit fragments: unit u = (f<<8) | (s<<5) | lane
    #pragma unroll
    for (int j = 0; j < 8; j++) {
        int u = j * 256 + tid;
        int f = u >> 8, s = (u >> 5) & 7, l = u & 31;
        int T0 = f * 16 + (l >> 2);
        int c0 = s * 16 + (l & 3) * 2;
        float v[4][2];
        v[0][0] = zt[(c0    ) * ZT_STRIDE + T0];
        v[0][1] = zt[(c0 + 1) * ZT_STRIDE + T0];
        v[1][0] = zt[(c0    ) * ZT_STRIDE + T0 + 8];
        v[1][1] = zt[(c0 + 1) * ZT_STRIDE + T0 + 8];
        v[2][0] = zt[(c0 + 8) * ZT_STRIDE + T0];
        v[2][1] = zt[(c0 + 9) * ZT_STRIDE + T0];
        v[3][0] = zt[(c0 + 8) * ZT_STRIDE + T0 + 8];
        v[3][1] = zt[(c0 + 9) * ZT_STRIDE + T0 + 8];
        uint32_t rh[4], rl[4];
        #pragma unroll
        for (int r = 0; r < 4; r++) {
            float h0 = __bfloat162float(__float2bfloat16(v[r][0]));
            float h1 = __bfloat162float(__float2bfloat16(v[r][1]));
            rh[r] = packbf(h0, h1);
            rl[r] = packbf(v[r][0] - h0, v[r][1] - h1);
        }
        g_Ah[ctaM * 2048 + u] = make_uint4(rh[0], rh[1], rh[2], rh[3]);
        g_Al[ctaM * 2048 + u] = make_uint4(rl[0], rl[1], rl[2], rl[3]);
    }
}

// ---------------- codebook -> bf16 hi/lo, mma-fragment-packed ----------------
// thread per (code, d-pair). B frag (col-major n8k16): lane l holds
// b0 = (k=2(l&3),+1, n=l>>2), b1 = (k+8,+9, n). Pack 2 n-frags per uint4.
__global__ void prep_cb_kernel(const float* __restrict__ cb) {
    int i = blockIdx.x * blockDim.x + threadIdx.x;    // < 65536
    int k = i >> 6;
    int d = (i & 63) * 2;
    float v0 = cb[k * D_DIM + d];
    float v1 = cb[k * D_DIM + d + 1];
    float h0 = __bfloat162float(__float2bfloat16(v0));
    float h1 = __bfloat162float(__float2bfloat16(v1));
    uint32_t ph = packbf(h0, h1);
    uint32_t pl = packbf(v0 - h0, v1 - h1);

    int tile = k >> 6, c = k & 63;
    int nf = c >> 3, np = nf >> 1, nin = c & 7;
    int s  = d >> 4, dk = d & 15;
    int kb = dk >> 3, lq = (dk & 7) >> 1;
    int lane = nin * 4 + lq;
    int comp = (nf & 1) * 2 + kb;
    int idx  = (((tile * 8 + s) * 4 + np) * 32 + lane) * 4 + comp;
    g_Bh[idx] = ph;
    g_Bl[idx] = pl;
}

// ---------------- mma distance GEMM + argmin (best + 2nd best) ----------------
// 256 threads, tile 128 tok x 64 codes, warps 4x2 (warp tile 32x32),
// 16 code tiles, B double-buffered. 3 passes: hh, hl, lh (pass-outer order).
__global__ void __launch_bounds__(256, 1) argmin_mma_kernel() {
    extern __shared__ char smem[];
    const uint32_t smb = smem_u32(smem);
    const int tid = threadIdx.x;
    const int l   = tid & 31, w = tid >> 5;
    const int wr  = w & 3,    wc = w >> 2;
    const int lq  = l & 3,    lr = l >> 2;
    const int ctaM = blockIdx.x;

    // group 0: A hi/lo (64KB) + cnorm
    {
        const uint4* gAh = g_Ah + (size_t)ctaM * 2048;
        const uint4* gAl = g_Al + (size_t)ctaM * 2048;
        #pragma unroll
        for (int j = 0; j < 8; j++) {
            int c = j * 256 + tid;
            CP16(smb + SM_A + c * 16, gAh + c);
            CP16(smb + SM_A + 32768 + c * 16, gAl + c);
        }
        CP16(smb + SM_CN + tid * 16, g_cnorm + tid * 4);
        CP_COMMIT();
    }
    // group 1: B tile 0
    {
        const uint4* bh = (const uint4*)g_Bh;
        const uint4* bl = (const uint4*)g_Bl;
        #pragma unroll
        for (int j = 0; j < 4; j++) {
            int c = j * 256 + tid;
            CP16(smb + SM_B + c * 16, bh + c);
            CP16(smb + SM_B + 16384 + c * 16, bl + c);
        }
        CP_COMMIT();
    }

    float acc[2][4][4];
    float best [2][2] = {{3.4e38f, 3.4e38f}, {3.4e38f, 3.4e38f}};
    float best2[2][2] = {{3.4e38f, 3.4e38f}, {3.4e38f, 3.4e38f}};
    int   bidx [2][2] = {{0, 0}, {0, 0}};

    for (int t = 0; t < 16; t++) {
        if (t < 15) {   // prefetch next B tile
            const uint4* bh = (const uint4*)g_Bh + (t + 1) * 1024;
            const uint4* bl = (const uint4*)g_Bl + (t + 1) * 1024;
            uint32_t dst = smb + SM_B + ((t + 1) & 1) * 32768;
            #pragma unroll
            for (int j = 0; j < 4; j++) {
                int c = j * 256 + tid;
                CP16(dst + c * 16, bh + c);
                CP16(dst + 16384 + c * 16, bl + c);
            }
            CP_COMMIT();
            CP_WAIT1();
        } else {
            CP_WAIT0();
        }
        __syncthreads();

        #pragma unroll
        for (int m = 0; m < 2; m++)
            #pragma unroll
            for (int n = 0; n < 4; n++)
                #pragma unroll
                for (int e = 0; e < 4; e++) acc[m][n][e] = 0.f;

        const uint4* Ah4 = (const uint4*)(smem + SM_A);
        const uint4* Al4 = (const uint4*)(smem + SM_A + 32768);
        const uint4* Bh4 = (const uint4*)(smem + SM_B + (size_t)(t & 1) * 32768);
        const uint4* Bl4 = (const uint4*)(smem + SM_B + (size_t)(t & 1) * 32768 + 16384);

        #pragma unroll
        for (int s = 0; s < 8; s++) {
            uint4 A0h = Ah4[((wr * 2 + 0) * 8 + s) * 32 + l];
            uint4 A1h = Ah4[((wr * 2 + 1) * 8 + s) * 32 + l];
            uint4 A0l = Al4[((wr * 2 + 0) * 8 + s) * 32 + l];
            uint4 A1l = Al4[((wr * 2 + 1) * 8 + s) * 32 + l];
            uint4 B0h = Bh4[(s * 4 + wc * 2 + 0) * 32 + l];
            uint4 B1h = Bh4[(s * 4 + wc * 2 + 1) * 32 + l];
            uint4 B0l = Bl4[(s * 4 + wc * 2 + 0) * 32 + l];
            uint4 B1l = Bl4[(s * 4 + wc * 2 + 1) * 32 + l];

            uint32_t ah[2][4] = {{A0h.x, A0h.y, A0h.z, A0h.w}, {A1h.x, A1h.y, A1h.z, A1h.w}};
            uint32_t al[2][4] = {{A0l.x, A0l.y, A0l.z, A0l.w}, {A1l.x, A1l.y, A1l.z, A1l.w}};
            uint32_t bh[4][2] = {{B0h.x, B0h.y}, {B0h.z, B0h.w}, {B1h.x, B1h.y}, {B1h.z, B1h.w}};
            uint32_t bl[4][2] = {{B0l.x, B0l.y}, {B0l.z, B0l.w}, {B1l.x, B1l.y}, {B1l.z, B1l.w}};

            // pass-outer: 8 independent accumulators between reuses
            #pragma unroll
            for (int m = 0; m < 2; m++)
                #pragma unroll
                for (int n = 0; n < 4; n++) mma16(acc[m][n], ah[m], bh[n]);
            #pragma unroll
            for (int m = 0; m < 2; m++)
                #pragma unroll
                for (int n = 0; n < 4; n++) mma16(acc[m][n], ah[m], bl[n]);
            #pragma unroll
            for (int m = 0; m < 2; m++)
                #pragma unroll
                for (int n = 0; n < 4; n++) mma16(acc[m][n], al[m], bh[n]);
        }

        // fold this 64-code tile into running best/2nd-best
        const float* cn = (const float*)(smem + SM_CN);
        #pragma unroll
        for (int m = 0; m < 2; m++)
            #pragma unroll
            for (int n = 0; n < 4; n++)
                #pragma unroll
                for (int e = 0; e < 4; e++) {
                    int code = t * 64 + (wc * 4 + n) * 8 + lq * 2 + (e & 1);
                    float dist = fmaf(-2.f, acc[m][n][e], cn[code]);
                    int rb = e >> 1;
                    merge3(best[m][rb], bidx[m][rb], best2[m][rb], dist, code);
                }
        __syncthreads();
    }

    // quad reduction (lanes xor 1,2 share rows, differ in cols)
    float* redv = (float*)(smem + SM_REDV);
    int*   redi = (int*)(smem + SM_REDI);
    float* red2 = (float*)(smem + SM_RED2);
    #pragma unroll
    for (int m = 0; m < 2; m++)
        #pragma unroll
        for (int rb = 0; rb < 2; rb++) {
            float v1 = best[m][rb], v2 = best2[m][rb];
            int   id = bidx[m][rb];
            #pragma unroll
            for (int off = 1; off <= 2; off <<= 1) {
                float ov1 = __shfl_xor_sync(0xffffffffu, v1, off);
                float ov2 = __shfl_xor_sync(0xffffffffu, v2, off);
                int   oi  = __shfl_xor_sync(0xffffffffu, id, off);
                merge3(v1, id, v2, ov1, oi);
                merge3(v1, id, v2, ov2, 0x7fffffff);
            }
            if (lq == 0) {
                int row = wr * 32 + m * 16 + rb * 8 + lr;
                redv[wc * 128 + row] = v1;
                redi[wc * 128 + row] = id;
                red2[wc * 128 + row] = v2;
            }
        }
    __syncthreads();
    if (tid < 128) {
        float v1 = redv[tid],       s1 = red2[tid];
        float w1 = redv[128 + tid], w2 = red2[128 + tid];
        int   i1 = redi[tid],       j1 = redi[128 + tid];
        merge3(v1, i1, s1, w1, j1);
        merge3(v1, i1, s1, w2, 0x7fffffff);
        int token = ctaM * 128 + tid;
        g_idx[token] = i1;
        if (s1 - v1 < EPS_FLAG) {
            int p = atomicAdd(&g_fixcnt, 1);
            g_fixlist[p] = token;
        }
    }
}

// ---------------- exact fp32 recompute for near-tie tokens ----------------
__global__ void fixup_kernel(const float* __restrict__ z,
                             const float* __restrict__ cb) {
    __shared__ float zz[D_DIM];
    __shared__ float rv[4];
    __shared__ int   ri[4];
    int cnt = g_fixcnt;
    for (int it = blockIdx.x; it < cnt; it += gridDim.x) {
        int token = g_fixlist[it];
        int b = token >> 10, s = token & 1023;
        int d = threadIdx.x;
        zz[d] = z[(size_t)b * 131072 + (size_t)d * 1024 + s];
        __syncthreads();

        float bv = 3.4e38f;
        int   bi = 0;
        #pragma unroll 1
        for (int j = 0; j < 8; j++) {
            int k = d * 8 + j;
            const float* cp = &cb[k * D_DIM];
            float dot = 0.f;
            #pragma unroll
            for (int q = 0; q < D_DIM; q++) dot = fmaf(zz[q], cp[q], dot);
            float dist = fmaf(-2.f, dot, g_cnorm[k]);
            if (dist < bv) { bv = dist; bi = k; }
        }
        #pragma unroll
        for (int off = 16; off; off >>= 1) {
            float ov = __shfl_xor_sync(0xffffffffu, bv, off);
            int   oi = __shfl_xor_sync(0xffffffffu, bi, off);
            if (ov < bv || (ov == bv && oi < bi)) { bv = ov; bi = oi; }
        }
        if ((d & 31) == 0) { rv[d >> 5] = bv; ri[d >> 5] = bi; }
        __syncthreads();
        if (d == 0) {
            for (int q = 1; q < 4; q++)
                if (rv[q] < bv || (rv[q] == bv && ri[q] < bi)) { bv = rv[q]; bi = ri[q]; }
            g_idx[token] = bi;
        }
        __syncthreads();
    }
}

// ---------------- gather quantized + loss + counts + idx output ----------------
__global__ void quant_kernel(const float* __restrict__ z,
                             const float* __restrict__ cb,
                             float* __restrict__ out) {
    int n    = blockIdx.x * 8 + (threadIdx.x >> 5);
    int lane = threadIdx.x & 31;
    int k    = g_idx[n];

    float4 q = *(const float4*)&cb[k * D_DIM + lane * 4];
    size_t off = (size_t)n * D_DIM + lane * 4;
    *(float4*)&out[Q_OFF + off] = q;

    float4 zz = *(const float4*)&z[off];
    float dx = q.x - zz.x, dy = q.y - zz.y, dz = q.z - zz.z, dw = q.w - zz.w;
    float s = dx * dx + dy * dy + dz * dz + dw * dw;
    #pragma unroll
    for (int o = 16; o; o >>= 1) s += __shfl_xor_sync(0xffffffffu, s, o);

    __shared__ float ws[8];
    if (lane == 0) {
        ws[threadIdx.x >> 5] = s;
        atomicAdd(&g_counts[k], 1.f);
        out[IDX_OFF + n] = (float)k;
    }
    __syncthreads();
    if (threadIdx.x == 0) {
        float t = 0.f;
        #pragma unroll
        for (int i = 0; i < 8; i++) t += ws[i];
        atomicAdd(&g_loss, t);
    }
}

// ---------------- dw scatter ----------------
__global__ void dw_kernel(const float* __restrict__ z) {
    int i = blockIdx.x * blockDim.x + threadIdx.x;
    int s = i & 1023;
    int d = (i >> 10) & 127;
    int b = i >> 17;
    int n = (b << 10) + s;
    int k = g_idx[n];
    atomicAdd(&g_dw[k * D_DIM + d], z[i]);
}

// ---------------- EMA count update + weights + losses ----------------
__global__ void finalize1_kernel(const float* __restrict__ ema_count,
                                 float* __restrict__ out) {
    int k = threadIdx.x;
    float c = EMA * ema_count[k] + (1.f - EMA) * g_counts[k];
    out[CNT_OFF + k] = c;

    __shared__ float sm[1024];
    sm[k] = c;
    __syncthreads();
    for (int o = 512; o; o >>= 1) {
        if (k < o) sm[k] += sm[k + o];
        __syncthreads();
    }
    float n = sm[0];
    g_weights[k] = (c + EPSV) / (n + K_CODES * EPSV) * n;

    if (k == 0) {
        float L = g_loss / 8388608.f;
        out[L_OFF]     = L;
        out[L_OFF + 1] = L;
    }
}

// ---------------- EMA weight update + new codebook ----------------
__global__ void finalize2_kernel(const float* __restrict__ ema_weight,
                                 float* __restrict__ out) {
    int i = blockIdx.x * blockDim.x + threadIdx.x;
    int k = i >> 7;
    float w = EMA * ema_weight[i] + (1.f - EMA) * g_dw[i];
    out[EMW_OFF + i] = w;
    out[CB_OFF + i]  = w / g_weights[k];
}

// ---------------- launch ----------------
extern "C" void kernel_launch(void* const* d_in, const int* in_sizes, int n_in,
                              void* d_out, int out_size) {
    const float* z          = (const float*)d_in[0];
    const float* cb         = (const float*)d_in[1];
    const float* ema_count  = (const float*)d_in[2];
    const float* ema_weight = (const float*)d_in[3];
    float* out = (float*)d_out;

    cudaFuncSetAttribute(argmin_mma_kernel,
                         cudaFuncAttributeMaxDynamicSharedMemorySize, SM_TOTAL);
    cudaFuncSetAttribute(prep_z_kernel,
                         cudaFuncAttributeMaxDynamicSharedMemorySize, 128 * ZT_STRIDE * 4);

    zero_kernel<<<512, 256>>>();
    prep_norm_kernel<<<K_CODES, D_DIM>>>(cb);
    prep_z_kernel<<<N_TOK / 128, 256, 128 * ZT_STRIDE * 4>>>(z);
    prep_cb_kernel<<<256, 256>>>(cb);
    argmin_mma_kernel<<<N_TOK / 128, 256, SM_TOTAL>>>();
    fixup_kernel<<<128, 128>>>(z, cb);
    quant_kernel<<<N_TOK / 8, 256>>>(z, cb, out);
    dw_kernel<<<Z_ELEMS / 256, 256>>>(z);
    finalize1_kernel<<<1, 1024>>>(ema_count, out);
    finalize2_kernel<<<512, 256>>>(ema_weight, out);
}

// round 6
// speedup vs baseline: 2.1205x; 1.6051x over previous
#include <cuda_runtime.h>
#include <cuda_fp16.h>
#include <cstdint>

// ---------------- problem constants ----------------
#define K_CODES   1024
#define D_DIM     128
#define N_TOK     65536        // 64 * 32 * 32 tokens (BHWC order)
#define Z_ELEMS   8388608      // 64 * 128 * 32 * 32
#define EMA       0.99f
#define EPSV      1e-5f
#define EPS_FLAG  0.15f        // approx-gap threshold for exact recompute (7.8 sigma)

// ---------------- output layout (flattened reference tuple, fp32) ----------------
#define Q_OFF     0
#define IDX_OFF   8388608
#define L_OFF     8454144
#define CB_OFF    8454146
#define CNT_OFF   8585218
#define EMW_OFF   8586242

// ---------------- smem layout for argmin (bytes) ----------------
#define SM_A      0            // 32KB: A fp16 frag-packed
#define SM_B      32768        // 2 stages * 16KB
#define SM_CN     65536        // 1024 floats
#define SM_REDV   69632        // 256 floats (best)
#define SM_REDI   70656        // 256 ints  (best idx)
#define SM_RED2   71680        // 256 floats (second best)
#define SM_TOTAL  72704

// ---------------- global scratch ----------------
__device__ uint4    g_Ah[512 * 2048];     // z fp16, frag-packed [cta][f8][s8][lane32] (16.7MB)
__device__ uint32_t g_Bh[65536];          // cb fp16 [tile16][s8][np4][lane32][comp4] (256KB)
__device__ float    g_cnorm[K_CODES];
__device__ float    g_counts[K_CODES];
__device__ float    g_dw[K_CODES * D_DIM];
__device__ int      g_idx[N_TOK];
__device__ float    g_loss;
__device__ float    g_weights[K_CODES];
__device__ int      g_fixcnt;
__device__ int      g_fixlist[N_TOK];

// ---------------- helpers ----------------
__device__ __forceinline__ uint32_t smem_u32(const void* p) {
    uint32_t a;
    asm("{ .reg .u64 t; cvta.to.shared.u64 t, %1; cvt.u32.u64 %0, t; }" : "=r"(a) : "l"(p));
    return a;
}
__device__ __forceinline__ uint32_t packh(float a, float b) {
    __half2 t = __floats2half2_rn(a, b);   // x=a (low), y=b (high)
    return *(uint32_t*)&t;
}
__device__ __forceinline__ void mma16(float* c, const uint32_t* a, const uint32_t* b) {
    asm volatile("mma.sync.aligned.m16n8k16.row.col.f32.f16.f16.f32 "
                 "{%0,%1,%2,%3}, {%4,%5,%6,%7}, {%8,%9}, {%0,%1,%2,%3};"
                 : "+f"(c[0]), "+f"(c[1]), "+f"(c[2]), "+f"(c[3])
                 : "r"(a[0]), "r"(a[1]), "r"(a[2]), "r"(a[3]), "r"(b[0]), "r"(b[1]));
}
// merge candidate (v,id) into triple (b1,i1,b2); first-index tie-break
__device__ __forceinline__ void merge3(float& b1, int& i1, float& b2, float v, int id) {
    if (v < b1 || (v == b1 && id < i1)) { b2 = b1; b1 = v; i1 = id; }
    else if (v < b2) b2 = v;
}
#define CP16(dst, src) \
    asm volatile("cp.async.cg.shared.global [%0], [%1], 16;" :: "r"(dst), "l"(src) : "memory")
#define CP_COMMIT() asm volatile("cp.async.commit_group;" ::: "memory")
#define CP_WAIT1()  asm volatile("cp.async.wait_group 1;" ::: "memory")
#define CP_WAIT0()  asm volatile("cp.async.wait_group 0;" ::: "memory")

// ---------------- zero scratch ----------------
__global__ void zero_kernel() {
    int i = blockIdx.x * blockDim.x + threadIdx.x;
    if (i < K_CODES * D_DIM) g_dw[i] = 0.f;
    if (i < K_CODES)         g_counts[i] = 0.f;
    if (i == 0)            { g_loss = 0.f; g_fixcnt = 0; }
}

// ---------------- codebook squared norms (exact fp32) ----------------
__global__ void prep_norm_kernel(const float* __restrict__ cb) {
    int k = blockIdx.x, d = threadIdx.x;
    float v = cb[k * D_DIM + d];
    float sq = v * v;
    #pragma unroll
    for (int o = 16; o; o >>= 1) sq += __shfl_xor_sync(0xffffffffu, sq, o);
    __shared__ float ws[4];
    if ((d & 31) == 0) ws[d >> 5] = sq;
    __syncthreads();
    if (d == 0) g_cnorm[k] = ws[0] + ws[1] + ws[2] + ws[3];
}

// ---------------- z -> fp16, mma-fragment-packed ----------------
#define ZT_STRIDE 132
__global__ void __launch_bounds__(256) prep_z_kernel(const float* __restrict__ z) {
    extern __shared__ float zt[];                     // [128 d][ZT_STRIDE]
    const int tid  = threadIdx.x;
    const int ctaM = blockIdx.x;
    const int b  = ctaM >> 3;
    const int s0 = (ctaM & 7) << 7;
    const float* zp = z + (size_t)b * 131072 + s0;

    #pragma unroll
    for (int j = 0; j < 16; j++) {
        int u  = j * 256 + tid;
        int d  = u >> 5, t4 = (u & 31) << 2;
        float4 v = *(const float4*)&zp[(size_t)d * 1024 + t4];
        *(float4*)&zt[d * ZT_STRIDE + t4] = v;
    }
    __syncthreads();

    #pragma unroll
    for (int j = 0; j < 8; j++) {
        int u = j * 256 + tid;
        int f = u >> 8, s = (u >> 5) & 7, l = u & 31;
        int T0 = f * 16 + (l >> 2);
        int c0 = s * 16 + (l & 3) * 2;
        uint32_t rh[4];
        rh[0] = packh(zt[(c0    ) * ZT_STRIDE + T0],     zt[(c0 + 1) * ZT_STRIDE + T0]);
        rh[1] = packh(zt[(c0    ) * ZT_STRIDE + T0 + 8], zt[(c0 + 1) * ZT_STRIDE + T0 + 8]);
        rh[2] = packh(zt[(c0 + 8) * ZT_STRIDE + T0],     zt[(c0 + 9) * ZT_STRIDE + T0]);
        rh[3] = packh(zt[(c0 + 8) * ZT_STRIDE + T0 + 8], zt[(c0 + 9) * ZT_STRIDE + T0 + 8]);
        g_Ah[ctaM * 2048 + u] = make_uint4(rh[0], rh[1], rh[2], rh[3]);
    }
}

// ---------------- codebook -> fp16, mma-fragment-packed ----------------
__global__ void prep_cb_kernel(const float* __restrict__ cb) {
    int i = blockIdx.x * blockDim.x + threadIdx.x;    // < 65536
    int k = i >> 6;
    int d = (i & 63) * 2;
    uint32_t ph = packh(cb[k * D_DIM + d], cb[k * D_DIM + d + 1]);

    int tile = k >> 6, c = k & 63;
    int nf = c >> 3, np = nf >> 1, nin = c & 7;
    int s  = d >> 4, dk = d & 15;
    int kb = dk >> 3, lq = (dk & 7) >> 1;
    int lane = nin * 4 + lq;
    int comp = (nf & 1) * 2 + kb;
    g_Bh[(((tile * 8 + s) * 4 + np) * 32 + lane) * 4 + comp] = ph;
}

// ---------------- fp16 screening GEMM + argmin (best + 2nd best) ----------------
__global__ void __launch_bounds__(256, 2) argmin_mma_kernel() {
    extern __shared__ char smem[];
    const uint32_t smb = smem_u32(smem);
    const int tid = threadIdx.x;
    const int l   = tid & 31, w = tid >> 5;
    const int wr  = w & 3,    wc = w >> 2;
    const int lq  = l & 3,    lr = l >> 2;
    const int ctaM = blockIdx.x;

    // group 0: A (32KB) + cnorm
    {
        const uint4* gAh = g_Ah + (size_t)ctaM * 2048;
        #pragma unroll
        for (int j = 0; j < 8; j++) {
            int c = j * 256 + tid;
            CP16(smb + SM_A + c * 16, gAh + c);
        }
        CP16(smb + SM_CN + tid * 16, g_cnorm + tid * 4);
        CP_COMMIT();
    }
    // group 1: B tile 0
    {
        const uint4* bh = (const uint4*)g_Bh;
        #pragma unroll
        for (int j = 0; j < 4; j++) {
            int c = j * 256 + tid;
            CP16(smb + SM_B + c * 16, bh + c);
        }
        CP_COMMIT();
    }

    float acc[2][4][4];
    float best [2][2] = {{3.4e38f, 3.4e38f}, {3.4e38f, 3.4e38f}};
    float best2[2][2] = {{3.4e38f, 3.4e38f}, {3.4e38f, 3.4e38f}};
    int   bidx [2][2] = {{0, 0}, {0, 0}};

    for (int t = 0; t < 16; t++) {
        if (t < 15) {
            const uint4* bh = (const uint4*)g_Bh + (t + 1) * 1024;
            uint32_t dst = smb + SM_B + ((t + 1) & 1) * 16384;
            #pragma unroll
            for (int j = 0; j < 4; j++) {
                int c = j * 256 + tid;
                CP16(dst + c * 16, bh + c);
            }
            CP_COMMIT();
            CP_WAIT1();
        } else {
            CP_WAIT0();
        }
        __syncthreads();

        #pragma unroll
        for (int m = 0; m < 2; m++)
            #pragma unroll
            for (int n = 0; n < 4; n++)
                #pragma unroll
                for (int e = 0; e < 4; e++) acc[m][n][e] = 0.f;

        const uint4* Ah4 = (const uint4*)(smem + SM_A);
        const uint4* Bh4 = (const uint4*)(smem + SM_B + (size_t)(t & 1) * 16384);

        #pragma unroll
        for (int s = 0; s < 8; s++) {
            uint4 A0 = Ah4[((wr * 2 + 0) * 8 + s) * 32 + l];
            uint4 A1 = Ah4[((wr * 2 + 1) * 8 + s) * 32 + l];
            uint4 B0 = Bh4[(s * 4 + wc * 2 + 0) * 32 + l];
            uint4 B1 = Bh4[(s * 4 + wc * 2 + 1) * 32 + l];

            uint32_t ah[2][4] = {{A0.x, A0.y, A0.z, A0.w}, {A1.x, A1.y, A1.z, A1.w}};
            uint32_t bh[4][2] = {{B0.x, B0.y}, {B0.z, B0.w}, {B1.x, B1.y}, {B1.z, B1.w}};

            #pragma unroll
            for (int m = 0; m < 2; m++)
                #pragma unroll
                for (int n = 0; n < 4; n++) mma16(acc[m][n], ah[m], bh[n]);
        }

        const float* cn = (const float*)(smem + SM_CN);
        #pragma unroll
        for (int m = 0; m < 2; m++)
            #pragma unroll
            for (int n = 0; n < 4; n++)
                #pragma unroll
                for (int e = 0; e < 4; e++) {
                    int code = t * 64 + (wc * 4 + n) * 8 + lq * 2 + (e & 1);
                    float dist = fmaf(-2.f, acc[m][n][e], cn[code]);
                    int rb = e >> 1;
                    merge3(best[m][rb], bidx[m][rb], best2[m][rb], dist, code);
                }
        __syncthreads();
    }

    float* redv = (float*)(smem + SM_REDV);
    int*   redi = (int*)(smem + SM_REDI);
    float* red2 = (float*)(smem + SM_RED2);
    #pragma unroll
    for (int m = 0; m < 2; m++)
        #pragma unroll
        for (int rb = 0; rb < 2; rb++) {
            float v1 = best[m][rb], v2 = best2[m][rb];
            int   id = bidx[m][rb];
            #pragma unroll
            for (int off = 1; off <= 2; off <<= 1) {
                float ov1 = __shfl_xor_sync(0xffffffffu, v1, off);
                float ov2 = __shfl_xor_sync(0xffffffffu, v2, off);
                int   oi  = __shfl_xor_sync(0xffffffffu, id, off);
                merge3(v1, id, v2, ov1, oi);
                merge3(v1, id, v2, ov2, 0x7fffffff);
            }
            if (lq == 0) {
                int row = wr * 32 + m * 16 + rb * 8 + lr;
                redv[wc * 128 + row] = v1;
                redi[wc * 128 + row] = id;
                red2[wc * 128 + row] = v2;
            }
        }
    __syncthreads();
    if (tid < 128) {
        float v1 = redv[tid],       s1 = red2[tid];
        float w1 = redv[128 + tid], w2 = red2[128 + tid];
        int   i1 = redi[tid],       j1 = redi[128 + tid];
        merge3(v1, i1, s1, w1, j1);
        merge3(v1, i1, s1, w2, 0x7fffffff);
        int token = ctaM * 128 + tid;
        g_idx[token] = i1;
        if (s1 - v1 < EPS_FLAG) {
            int p = atomicAdd(&g_fixcnt, 1);
            g_fixlist[p] = token;
        }
    }
}

// ---------------- exact fp32 recompute, tile-batched (16 tokens/block) ----------------
#define FIX_G 16
#define CB_STR 132
__global__ void __launch_bounds__(256) fixup_kernel(const float* __restrict__ z,
                                                    const float* __restrict__ cb) {
    __shared__ float ztok[FIX_G][D_DIM];
    __shared__ float cbt[64 * CB_STR];
    __shared__ float cnt_[64];
    const int tid = threadIdx.x;
    const int tk = tid >> 4, cs = tid & 15;
    int cnt = g_fixcnt;
    int nIter = (cnt + FIX_G - 1) / FIX_G;

    for (int it = blockIdx.x; it < nIter; it += gridDim.x) {
        int base = it * FIX_G;
        // load up to 16 tokens' z rows
        for (int u = tid; u < FIX_G * D_DIM; u += 256) {
            int tt = u >> 7, d = u & 127;
            float v = 0.f;
            int ti = base + tt;
            if (ti < cnt) {
                int token = g_fixlist[ti];
                int b = token >> 10, s = token & 1023;
                v = z[(size_t)b * 131072 + (size_t)d * 1024 + s];
            }
            ztok[tt][d] = v;
        }

        float bv = 3.4e38f;
        int   bi = 0;
        for (int tile = 0; tile < 16; tile++) {
            __syncthreads();
            for (int u = tid; u < 2048; u += 256) {   // 64 codes x 128 d as float4
                float4 vv = ((const float4*)cb)[tile * 2048 + u];
                *(float4*)&cbt[(u >> 5) * CB_STR + (u & 31) * 4] = vv;
            }
            if (tid < 64) cnt_[tid] = g_cnorm[tile * 64 + tid];
            __syncthreads();

            float dot[4] = {0.f, 0.f, 0.f, 0.f};
            const float* zp = ztok[tk];
            #pragma unroll 4
            for (int q = 0; q < D_DIM; q++) {
                float zv = zp[q];
                #pragma unroll
                for (int j = 0; j < 4; j++)
                    dot[j] = fmaf(zv, cbt[(cs + j * 16) * CB_STR + q], dot[j]);
            }
            #pragma unroll
            for (int j = 0; j < 4; j++) {
                int c = cs + j * 16;
                float dist = fmaf(-2.f, dot[j], cnt_[c]);
                int code = tile * 64 + c;
                if (dist < bv || (dist == bv && code < bi)) { bv = dist; bi = code; }
            }
        }
        // reduce the 16 threads of this token (contiguous lanes in warp)
        #pragma unroll
        for (int off = 1; off < 16; off <<= 1) {
            float ov = __shfl_xor_sync(0xffffffffu, bv, off);
            int   oi = __shfl_xor_sync(0xffffffffu, bi, off);
            if (ov < bv || (ov == bv && oi < bi)) { bv = ov; bi = oi; }
        }
        if (cs == 0 && base + tk < cnt) g_idx[g_fixlist[base + tk]] = bi;
        __syncthreads();
    }
}

// ---------------- gather quantized + loss + counts + idx output ----------------
__global__ void quant_kernel(const float* __restrict__ z,
                             const float* __restrict__ cb,
                             float* __restrict__ out) {
    int n    = blockIdx.x * 8 + (threadIdx.x >> 5);
    int lane = threadIdx.x & 31;
    int k    = g_idx[n];

    float4 q = *(const float4*)&cb[k * D_DIM + lane * 4];
    size_t off = (size_t)n * D_DIM + lane * 4;
    *(float4*)&out[Q_OFF + off] = q;

    float4 zz = *(const float4*)&z[off];
    float dx = q.x - zz.x, dy = q.y - zz.y, dz = q.z - zz.z, dw = q.w - zz.w;
    float s = dx * dx + dy * dy + dz * dz + dw * dw;
    #pragma unroll
    for (int o = 16; o; o >>= 1) s += __shfl_xor_sync(0xffffffffu, s, o);

    __shared__ float ws[8];
    if (lane == 0) {
        ws[threadIdx.x >> 5] = s;
        atomicAdd(&g_counts[k], 1.f);
        out[IDX_OFF + n] = (float)k;
    }
    __syncthreads();
    if (threadIdx.x == 0) {
        float t = 0.f;
        #pragma unroll
        for (int i = 0; i < 8; i++) t += ws[i];
        atomicAdd(&g_loss, t);
    }
}

// ---------------- dw scatter ----------------
__global__ void dw_kernel(const float* __restrict__ z) {
    int i = blockIdx.x * blockDim.x + threadIdx.x;
    int s = i & 1023;
    int d = (i >> 10) & 127;
    int b = i >> 17;
    int n = (b << 10) + s;
    int k = g_idx[n];
    atomicAdd(&g_dw[k * D_DIM + d], z[i]);
}

// ---------------- EMA count update + weights + losses ----------------
__global__ void finalize1_kernel(const float* __restrict__ ema_count,
                                 float* __restrict__ out) {
    int k = threadIdx.x;
    float c = EMA * ema_count[k] + (1.f - EMA) * g_counts[k];
    out[CNT_OFF + k] = c;

    __shared__ float sm[1024];
    sm[k] = c;
    __syncthreads();
    for (int o = 512; o; o >>= 1) {
        if (k < o) sm[k] += sm[k + o];
        __syncthreads();
    }
    float n = sm[0];
    g_weights[k] = (c + EPSV) / (n + K_CODES * EPSV) * n;

    if (k == 0) {
        float L = g_loss / 8388608.f;
        out[L_OFF]     = L;
        out[L_OFF + 1] = L;
    }
}

// ---------------- EMA weight update + new codebook ----------------
__global__ void finalize2_kernel(const float* __restrict__ ema_weight,
                                 float* __restrict__ out) {
    int i = blockIdx.x * blockDim.x + threadIdx.x;
    int k = i >> 7;
    float w = EMA * ema_weight[i] + (1.f - EMA) * g_dw[i];
    out[EMW_OFF + i] = w;
    out[CB_OFF + i]  = w / g_weights[k];
}

// ---------------- launch ----------------
extern "C" void kernel_launch(void* const* d_in, const int* in_sizes, int n_in,
                              void* d_out, int out_size) {
    const float* z          = (const float*)d_in[0];
    const float* cb         = (const float*)d_in[1];
    const float* ema_count  = (const float*)d_in[2];
    const float* ema_weight = (const float*)d_in[3];
    float* out = (float*)d_out;

    cudaFuncSetAttribute(argmin_mma_kernel,
                         cudaFuncAttributeMaxDynamicSharedMemorySize, SM_TOTAL);
    cudaFuncSetAttribute(prep_z_kernel,
                         cudaFuncAttributeMaxDynamicSharedMemorySize, 128 * ZT_STRIDE * 4);

    zero_kernel<<<512, 256>>>();
    prep_norm_kernel<<<K_CODES, D_DIM>>>(cb);
    prep_z_kernel<<<N_TOK / 128, 256, 128 * ZT_STRIDE * 4>>>(z);
    prep_cb_kernel<<<256, 256>>>(cb);
    argmin_mma_kernel<<<N_TOK / 128, 256, SM_TOTAL>>>();
    fixup_kernel<<<256, 256>>>(z, cb);
    quant_kernel<<<N_TOK / 8, 256>>>(z, cb, out);
    dw_kernel<<<Z_ELEMS / 256, 256>>>(z);
    finalize1_kernel<<<1, 1024>>>(ema_count, out);
    finalize2_kernel<<<512, 256>>>(ema_weight, out);
}

// round 7
// speedup vs baseline: 2.9993x; 1.4144x over previous
#include <cuda_runtime.h>
#include <cuda_fp16.h>
#include <cstdint>

// ---------------- problem constants ----------------
#define K_CODES   1024
#define D_DIM     128
#define N_TOK     65536        // 64 * 32 * 32 tokens (BHWC order)
#define Z_ELEMS   8388608      // 64 * 128 * 32 * 32
#define EMA       0.99f
#define EPSV      1e-5f
#define EPS_FLAG  0.15f        // approx-gap threshold for exact recompute (7.8 sigma)

// ---------------- output layout (flattened reference tuple, fp32) ----------------
#define Q_OFF     0
#define IDX_OFF   8388608
#define L_OFF     8454144
#define CB_OFF    8454146
#define CNT_OFF   8585218
#define EMW_OFF   8586242

// ---------------- smem layout for argmin (bytes) ----------------
#define SM_A      0            // 32KB: A fp16 frag-packed
#define SM_B      32768        // 2 stages * 16KB
#define SM_CN     65536        // 1024 floats
#define SM_REDV   69632        // 256 floats (best)
#define SM_REDI   70656        // 256 ints  (best idx)
#define SM_RED2   71680        // 256 floats (second best)
#define SM_TOTAL  72704

// ---------------- global scratch ----------------
__device__ uint4    g_Ah[512 * 2048];     // z fp16, frag-packed [cta][f8][s8][lane32] (16.7MB)
__device__ uint32_t g_Bh[65536];          // cb fp16 [tile16][s8][np4][lane32][comp4] (256KB)
__device__ float    g_cnorm[K_CODES];
__device__ float    g_counts[K_CODES];
__device__ float    g_dw[K_CODES * D_DIM];
__device__ int      g_idx[N_TOK];
__device__ float    g_loss;
__device__ float    g_weights[K_CODES];
__device__ int      g_fixcnt;
__device__ int      g_fixlist[N_TOK];

// ---------------- helpers ----------------
__device__ __forceinline__ uint32_t smem_u32(const void* p) {
    uint32_t a;
    asm("{ .reg .u64 t; cvta.to.shared.u64 t, %1; cvt.u32.u64 %0, t; }" : "=r"(a) : "l"(p));
    return a;
}
__device__ __forceinline__ uint32_t packh(float a, float b) {
    __half2 t = __floats2half2_rn(a, b);   // x=a (low), y=b (high)
    return *(uint32_t*)&t;
}
__device__ __forceinline__ void mma16(float* c, const uint32_t* a, const uint32_t* b) {
    asm volatile("mma.sync.aligned.m16n8k16.row.col.f32.f16.f16.f32 "
                 "{%0,%1,%2,%3}, {%4,%5,%6,%7}, {%8,%9}, {%0,%1,%2,%3};"
                 : "+f"(c[0]), "+f"(c[1]), "+f"(c[2]), "+f"(c[3])
                 : "r"(a[0]), "r"(a[1]), "r"(a[2]), "r"(a[3]), "r"(b[0]), "r"(b[1]));
}
// merge candidate (v,id) into triple (b1,i1,b2); first-index tie-break
__device__ __forceinline__ void merge3(float& b1, int& i1, float& b2, float v, int id) {
    if (v < b1 || (v == b1 && id < i1)) { b2 = b1; b1 = v; i1 = id; }
    else if (v < b2) b2 = v;
}
#define CP16(dst, src) \
    asm volatile("cp.async.cg.shared.global [%0], [%1], 16;" :: "r"(dst), "l"(src) : "memory")
#define CP_COMMIT() asm volatile("cp.async.commit_group;" ::: "memory")
#define CP_WAIT1()  asm volatile("cp.async.wait_group 1;" ::: "memory")
#define CP_WAIT0()  asm volatile("cp.async.wait_group 0;" ::: "memory")

// ---------------- fused prep: zero + cnorm + fp16 cb fragments ----------------
// 1024 blocks x 128 threads; block = code k.
__global__ void __launch_bounds__(128) prep_all_kernel(const float* __restrict__ cb) {
    const int k = blockIdx.x, d = threadIdx.x;
    float v = cb[k * D_DIM + d];

    // zero scratch rows
    g_dw[k * D_DIM + d] = 0.f;
    if (d == 0) g_counts[k] = 0.f;
    if (k == 0 && d == 0) { g_loss = 0.f; g_fixcnt = 0; }

    // pair value for fp16 pack (even lanes pick up odd neighbor)
    float vn = __shfl_xor_sync(0xffffffffu, v, 1);

    // squared norm reduce
    float sq = v * v;
    #pragma unroll
    for (int o = 16; o; o >>= 1) sq += __shfl_xor_sync(0xffffffffu, sq, o);
    __shared__ float ws[4];
    if ((d & 31) == 0) ws[d >> 5] = sq;
    __syncthreads();
    if (d == 0) g_cnorm[k] = ws[0] + ws[1] + ws[2] + ws[3];

    // fp16 fragment pack (even d writes pair (d, d+1))
    if ((d & 1) == 0) {
        uint32_t ph = packh(v, vn);
        int tile = k >> 6, c = k & 63;
        int nf = c >> 3, np = nf >> 1, nin = c & 7;
        int s  = d >> 4, dk = d & 15;
        int kb = dk >> 3, lq = (dk & 7) >> 1;
        int lane = nin * 4 + lq;
        int comp = (nf & 1) * 2 + kb;
        g_Bh[(((tile * 8 + s) * 4 + np) * 32 + lane) * 4 + comp] = ph;
    }
}

// ---------------- z -> fp16, mma-fragment-packed ----------------
#define ZT_STRIDE 132
__global__ void __launch_bounds__(256) prep_z_kernel(const float* __restrict__ z) {
    extern __shared__ float zt[];                     // [128 d][ZT_STRIDE]
    const int tid  = threadIdx.x;
    const int ctaM = blockIdx.x;
    const int b  = ctaM >> 3;
    const int s0 = (ctaM & 7) << 7;
    const float* zp = z + (size_t)b * 131072 + s0;

    #pragma unroll
    for (int j = 0; j < 16; j++) {
        int u  = j * 256 + tid;
        int d  = u >> 5, t4 = (u & 31) << 2;
        float4 v = *(const float4*)&zp[(size_t)d * 1024 + t4];
        *(float4*)&zt[d * ZT_STRIDE + t4] = v;
    }
    __syncthreads();

    #pragma unroll
    for (int j = 0; j < 8; j++) {
        int u = j * 256 + tid;
        int f = u >> 8, s = (u >> 5) & 7, l = u & 31;
        int T0 = f * 16 + (l >> 2);
        int c0 = s * 16 + (l & 3) * 2;
        uint32_t rh[4];
        rh[0] = packh(zt[(c0    ) * ZT_STRIDE + T0],     zt[(c0 + 1) * ZT_STRIDE + T0]);
        rh[1] = packh(zt[(c0    ) * ZT_STRIDE + T0 + 8], zt[(c0 + 1) * ZT_STRIDE + T0 + 8]);
        rh[2] = packh(zt[(c0 + 8) * ZT_STRIDE + T0],     zt[(c0 + 9) * ZT_STRIDE + T0]);
        rh[3] = packh(zt[(c0 + 8) * ZT_STRIDE + T0 + 8], zt[(c0 + 9) * ZT_STRIDE + T0 + 8]);
        g_Ah[ctaM * 2048 + u] = make_uint4(rh[0], rh[1], rh[2], rh[3]);
    }
}

// ---------------- fp16 screening GEMM + argmin (best + 2nd best) ----------------
__global__ void __launch_bounds__(256, 2) argmin_mma_kernel() {
    extern __shared__ char smem[];
    const uint32_t smb = smem_u32(smem);
    const int tid = threadIdx.x;
    const int l   = tid & 31, w = tid >> 5;
    const int wr  = w & 3,    wc = w >> 2;
    const int lq  = l & 3,    lr = l >> 2;
    const int ctaM = blockIdx.x;

    // group 0: A (32KB) + cnorm
    {
        const uint4* gAh = g_Ah + (size_t)ctaM * 2048;
        #pragma unroll
        for (int j = 0; j < 8; j++) {
            int c = j * 256 + tid;
            CP16(smb + SM_A + c * 16, gAh + c);
        }
        CP16(smb + SM_CN + tid * 16, g_cnorm + tid * 4);
        CP_COMMIT();
    }
    // group 1: B tile 0
    {
        const uint4* bh = (const uint4*)g_Bh;
        #pragma unroll
        for (int j = 0; j < 4; j++) {
            int c = j * 256 + tid;
            CP16(smb + SM_B + c * 16, bh + c);
        }
        CP_COMMIT();
    }

    float acc[2][4][4];
    float best [2][2] = {{3.4e38f, 3.4e38f}, {3.4e38f, 3.4e38f}};
    float best2[2][2] = {{3.4e38f, 3.4e38f}, {3.4e38f, 3.4e38f}};
    int   bidx [2][2] = {{0, 0}, {0, 0}};

    for (int t = 0; t < 16; t++) {
        if (t < 15) {
            const uint4* bh = (const uint4*)g_Bh + (t + 1) * 1024;
            uint32_t dst = smb + SM_B + ((t + 1) & 1) * 16384;
            #pragma unroll
            for (int j = 0; j < 4; j++) {
                int c = j * 256 + tid;
                CP16(dst + c * 16, bh + c);
            }
            CP_COMMIT();
            CP_WAIT1();
        } else {
            CP_WAIT0();
        }
        __syncthreads();

        #pragma unroll
        for (int m = 0; m < 2; m++)
            #pragma unroll
            for (int n = 0; n < 4; n++)
                #pragma unroll
                for (int e = 0; e < 4; e++) acc[m][n][e] = 0.f;

        const uint4* Ah4 = (const uint4*)(smem + SM_A);
        const uint4* Bh4 = (const uint4*)(smem + SM_B + (size_t)(t & 1) * 16384);

        #pragma unroll
        for (int s = 0; s < 8; s++) {
            uint4 A0 = Ah4[((wr * 2 + 0) * 8 + s) * 32 + l];
            uint4 A1 = Ah4[((wr * 2 + 1) * 8 + s) * 32 + l];
            uint4 B0 = Bh4[(s * 4 + wc * 2 + 0) * 32 + l];
            uint4 B1 = Bh4[(s * 4 + wc * 2 + 1) * 32 + l];

            uint32_t ah[2][4] = {{A0.x, A0.y, A0.z, A0.w}, {A1.x, A1.y, A1.z, A1.w}};
            uint32_t bh[4][2] = {{B0.x, B0.y}, {B0.z, B0.w}, {B1.x, B1.y}, {B1.z, B1.w}};

            #pragma unroll
            for (int m = 0; m < 2; m++)
                #pragma unroll
                for (int n = 0; n < 4; n++) mma16(acc[m][n], ah[m], bh[n]);
        }

        const float* cn = (const float*)(smem + SM_CN);
        #pragma unroll
        for (int m = 0; m < 2; m++)
            #pragma unroll
            for (int n = 0; n < 4; n++)
                #pragma unroll
                for (int e = 0; e < 4; e++) {
                    int code = t * 64 + (wc * 4 + n) * 8 + lq * 2 + (e & 1);
                    float dist = fmaf(-2.f, acc[m][n][e], cn[code]);
                    int rb = e >> 1;
                    merge3(best[m][rb], bidx[m][rb], best2[m][rb], dist, code);
                }
        __syncthreads();
    }

    float* redv = (float*)(smem + SM_REDV);
    int*   redi = (int*)(smem + SM_REDI);
    float* red2 = (float*)(smem + SM_RED2);
    #pragma unroll
    for (int m = 0; m < 2; m++)
        #pragma unroll
        for (int rb = 0; rb < 2; rb++) {
            float v1 = best[m][rb], v2 = best2[m][rb];
            int   id = bidx[m][rb];
            #pragma unroll
            for (int off = 1; off <= 2; off <<= 1) {
                float ov1 = __shfl_xor_sync(0xffffffffu, v1, off);
                float ov2 = __shfl_xor_sync(0xffffffffu, v2, off);
                int   oi  = __shfl_xor_sync(0xffffffffu, id, off);
                merge3(v1, id, v2, ov1, oi);
                merge3(v1, id, v2, ov2, 0x7fffffff);
            }
            if (lq == 0) {
                int row = wr * 32 + m * 16 + rb * 8 + lr;
                redv[wc * 128 + row] = v1;
                redi[wc * 128 + row] = id;
                red2[wc * 128 + row] = v2;
            }
        }
    __syncthreads();
    if (tid < 128) {
        float v1 = redv[tid],       s1 = red2[tid];
        float w1 = redv[128 + tid], w2 = red2[128 + tid];
        int   i1 = redi[tid],       j1 = redi[128 + tid];
        merge3(v1, i1, s1, w1, j1);
        merge3(v1, i1, s1, w2, 0x7fffffff);
        int token = ctaM * 128 + tid;
        g_idx[token] = i1;
        if (s1 - v1 < EPS_FLAG) {
            int p = atomicAdd(&g_fixcnt, 1);
            g_fixlist[p] = token;
        }
    }
}

// ---------------- exact fp32 recompute, tile-batched (16 tokens/block) ----------------
#define FIX_G 16
#define CB_STR 132
__global__ void __launch_bounds__(256) fixup_kernel(const float* __restrict__ z,
                                                    const float* __restrict__ cb) {
    __shared__ float ztok[FIX_G][D_DIM];
    __shared__ float cbt[64 * CB_STR];
    __shared__ float cnt_[64];
    const int tid = threadIdx.x;
    const int tk = tid >> 4, cs = tid & 15;
    int cnt = g_fixcnt;
    int nIter = (cnt + FIX_G - 1) / FIX_G;

    for (int it = blockIdx.x; it < nIter; it += gridDim.x) {
        int base = it * FIX_G;
        for (int u = tid; u < FIX_G * D_DIM; u += 256) {
            int tt = u >> 7, d = u & 127;
            float v = 0.f;
            int ti = base + tt;
            if (ti < cnt) {
                int token = g_fixlist[ti];
                int b = token >> 10, s = token & 1023;
                v = z[(size_t)b * 131072 + (size_t)d * 1024 + s];
            }
            ztok[tt][d] = v;
        }

        float bv = 3.4e38f;
        int   bi = 0;
        for (int tile = 0; tile < 16; tile++) {
            __syncthreads();
            for (int u = tid; u < 2048; u += 256) {
                float4 vv = ((const float4*)cb)[tile * 2048 + u];
                *(float4*)&cbt[(u >> 5) * CB_STR + (u & 31) * 4] = vv;
            }
            if (tid < 64) cnt_[tid] = g_cnorm[tile * 64 + tid];
            __syncthreads();

            float dot[4] = {0.f, 0.f, 0.f, 0.f};
            const float* zp = ztok[tk];
            #pragma unroll 4
            for (int q = 0; q < D_DIM; q++) {
                float zv = zp[q];
                #pragma unroll
                for (int j = 0; j < 4; j++)
                    dot[j] = fmaf(zv, cbt[(cs + j * 16) * CB_STR + q], dot[j]);
            }
            #pragma unroll
            for (int j = 0; j < 4; j++) {
                int c = cs + j * 16;
                float dist = fmaf(-2.f, dot[j], cnt_[c]);
                int code = tile * 64 + c;
                if (dist < bv || (dist == bv && code < bi)) { bv = dist; bi = code; }
            }
        }
        #pragma unroll
        for (int off = 1; off < 16; off <<= 1) {
            float ov = __shfl_xor_sync(0xffffffffu, bv, off);
            int   oi = __shfl_xor_sync(0xffffffffu, bi, off);
            if (ov < bv || (ov == bv && oi < bi)) { bv = ov; bi = oi; }
        }
        if (cs == 0 && base + tk < cnt) g_idx[g_fixlist[base + tk]] = bi;
        __syncthreads();
    }
}

// ---------------- gather quantized + loss + counts + idx (2 tokens/warp) ----------------
__global__ void __launch_bounds__(256) quant_kernel(const float* __restrict__ z,
                                                    const float* __restrict__ cb,
                                                    float* __restrict__ out) {
    int wid  = threadIdx.x >> 5;
    int lane = threadIdx.x & 31;
    int n0   = blockIdx.x * 16 + wid * 2;

    int k0 = g_idx[n0];
    int k1 = g_idx[n0 + 1];

    float4 q0 = *(const float4*)&cb[k0 * D_DIM + lane * 4];
    float4 q1 = *(const float4*)&cb[k1 * D_DIM + lane * 4];
    size_t o0 = (size_t)n0 * D_DIM + lane * 4;
    float4 z0 = *(const float4*)&z[o0];
    float4 z1 = *(const float4*)&z[o0 + D_DIM];
    *(float4*)&out[Q_OFF + o0]         = q0;
    *(float4*)&out[Q_OFF + o0 + D_DIM] = q1;

    float dx = q0.x - z0.x, dy = q0.y - z0.y, dz = q0.z - z0.z, dw = q0.w - z0.w;
    float s  = dx * dx + dy * dy + dz * dz + dw * dw;
    dx = q1.x - z1.x; dy = q1.y - z1.y; dz = q1.z - z1.z; dw = q1.w - z1.w;
    s += dx * dx + dy * dy + dz * dz + dw * dw;
    #pragma unroll
    for (int o = 16; o; o >>= 1) s += __shfl_xor_sync(0xffffffffu, s, o);

    __shared__ float ws[8];
    if (lane == 0) {
        ws[wid] = s;
        atomicAdd(&g_counts[k0], 1.f);
        atomicAdd(&g_counts[k1], 1.f);
        out[IDX_OFF + n0]     = (float)k0;
        out[IDX_OFF + n0 + 1] = (float)k1;
    }
    __syncthreads();
    if (threadIdx.x == 0) {
        float t = 0.f;
        #pragma unroll
        for (int i = 0; i < 8; i++) t += ws[i];
        atomicAdd(&g_loss, t);
    }
}

// ---------------- dw scatter: vector red.v4 (4 d per thread) ----------------
__global__ void __launch_bounds__(256) dw_kernel(const float* __restrict__ z) {
    int u  = blockIdx.x * blockDim.x + threadIdx.x;   // < 2097152
    int s  = u & 1023;
    int dg = (u >> 10) & 31;
    int b  = u >> 15;
    int n  = (b << 10) + s;
    int k  = g_idx[n];
    const float* zp = z + (size_t)b * 131072 + (size_t)dg * 4096 + s;
    float v0 = zp[0], v1 = zp[1024], v2 = zp[2048], v3 = zp[3072];
    float* dst = &g_dw[k * D_DIM + dg * 4];
    asm volatile("red.global.add.v4.f32 [%0], {%1,%2,%3,%4};"
                 :: "l"(dst), "f"(v0), "f"(v1), "f"(v2), "f"(v3) : "memory");
}

// ---------------- EMA count update + weights + losses ----------------
__global__ void finalize1_kernel(const float* __restrict__ ema_count,
                                 float* __restrict__ out) {
    int k = threadIdx.x;
    float c = EMA * ema_count[k] + (1.f - EMA) * g_counts[k];
    out[CNT_OFF + k] = c;

    __shared__ float sm[1024];
    sm[k] = c;
    __syncthreads();
    for (int o = 512; o; o >>= 1) {
        if (k < o) sm[k] += sm[k + o];
        __syncthreads();
    }
    float n = sm[0];
    g_weights[k] = (c + EPSV) / (n + K_CODES * EPSV) * n;

    if (k == 0) {
        float L = g_loss / 8388608.f;
        out[L_OFF]     = L;
        out[L_OFF + 1] = L;
    }
}

// ---------------- EMA weight update + new codebook ----------------
__global__ void finalize2_kernel(const float* __restrict__ ema_weight,
                                 float* __restrict__ out) {
    int i = blockIdx.x * blockDim.x + threadIdx.x;
    int k = i >> 7;
    float w = EMA * ema_weight[i] + (1.f - EMA) * g_dw[i];
    out[EMW_OFF + i] = w;
    out[CB_OFF + i]  = w / g_weights[k];
}

// ---------------- launch ----------------
extern "C" void kernel_launch(void* const* d_in, const int* in_sizes, int n_in,
                              void* d_out, int out_size) {
    const float* z          = (const float*)d_in[0];
    const float* cb         = (const float*)d_in[1];
    const float* ema_count  = (const float*)d_in[2];
    const float* ema_weight = (const float*)d_in[3];
    float* out = (float*)d_out;

    cudaFuncSetAttribute(argmin_mma_kernel,
                         cudaFuncAttributeMaxDynamicSharedMemorySize, SM_TOTAL);
    cudaFuncSetAttribute(prep_z_kernel,
                         cudaFuncAttributeMaxDynamicSharedMemorySize, 128 * ZT_STRIDE * 4);

    prep_all_kernel<<<K_CODES, 128>>>(cb);
    prep_z_kernel<<<N_TOK / 128, 256, 128 * ZT_STRIDE * 4>>>(z);
    argmin_mma_kernel<<<N_TOK / 128, 256, SM_TOTAL>>>();
    fixup_kernel<<<256, 256>>>(z, cb);
    quant_kernel<<<N_TOK / 16, 256>>>(z, cb, out);
    dw_kernel<<<Z_ELEMS / 1024, 256>>>(z);
    finalize1_kernel<<<1, 1024>>>(ema_count, out);
    finalize2_kernel<<<512, 256>>>(ema_weight, out);
}